// round 1
// baseline (speedup 1.0000x reference)
#include <cuda_runtime.h>
#include <cstdint>

#define T_BATCH 32
#define OUT_DIM 8192
#define IN_DIM 8192
#define GS 128
#define ROWS_PER_CTA 16
#define WARPS 8
#define KSEG (IN_DIM / WARPS)   /* 1024 */
#define CHUNK 32
#define NCHUNK (KSEG / CHUNK)   /* 32 */

// Packed dual-FMA: acc(2xf32) += a(2xf32) * b(2xf32). Native f32x2 pipe on sm_103a.
__device__ __forceinline__ void ffma2(unsigned long long &acc,
                                      unsigned long long a,
                                      unsigned long long b) {
    asm("fma.rn.f32x2 %0, %1, %2, %0;" : "+l"(acc) : "l"(a), "l"(b));
}

__global__ __launch_bounds__(256, 2)
void ternary_linear_kernel(const float* __restrict__ x,
                           const int*   __restrict__ tern,
                           const float* __restrict__ scales,
                           float*       __restrict__ out) {
    // Per-warp staged, pre-scaled weights. Reused as the reduction buffer at the end.
    __shared__ float w_s[WARPS][ROWS_PER_CTA][CHUNK];

    const int tid  = threadIdx.x;
    const int lane = tid & 31;          // lane == batch row t
    const int warp = tid >> 5;          // warp == K segment
    const int o0   = blockIdx.x * ROWS_PER_CTA;
    const int k0   = warp * KSEG;

    unsigned long long acc[ROWS_PER_CTA];
    #pragma unroll
    for (int r = 0; r < ROWS_PER_CTA; r++) acc[r] = 0ULL;

    const float* xrow = x + lane * IN_DIM;

    for (int ch = 0; ch < NCHUNK; ch++) {
        const int i0 = k0 + ch * CHUNK;

        // x chunk -> registers (16B loads, per-lane contiguous, L1/L2-hot, reused over 16 rows)
        ulonglong2 xv[8];
        #pragma unroll
        for (int q = 0; q < 8; q++)
            xv[q] = *reinterpret_cast<const ulonglong2*>(xrow + i0 + q * 4);

        // Stage w = float(tern) * scale into smem (conversion cost amortized 32x by broadcast).
        // Chunk of 32 never crosses a 128-wide scale group since i0 % 32 == 0.
        const int g = i0 >> 7;
        #pragma unroll
        for (int r = 0; r < ROWS_PER_CTA; r++) {
            const int o = o0 + r;
            const int t = __ldg(tern + o * IN_DIM + i0 + lane);      // coalesced 128B
            const float s = __ldg(scales + o * (IN_DIM / GS) + g);   // uniform, L1-hot
            w_s[warp][r][lane] = (float)t * s;
        }
        __syncwarp();

        // Inner loop: broadcast LDS.128 + packed FFMA2. 16 FFMA2 per row-chunk.
        #pragma unroll
        for (int r = 0; r < ROWS_PER_CTA; r++) {
            #pragma unroll
            for (int q = 0; q < 8; q++) {
                ulonglong2 wq = *reinterpret_cast<const ulonglong2*>(&w_s[warp][r][q * 4]);
                ffma2(acc[r], xv[q].x, wq.x);
                ffma2(acc[r], xv[q].y, wq.y);
            }
        }
        __syncwarp();   // WAR guard before next chunk restages w_s
    }

    // CTA-level reduction across the 8 K-segments (deterministic, no atomics).
    __syncthreads();
    #pragma unroll
    for (int r = 0; r < ROWS_PER_CTA; r++) {
        const float lo = __uint_as_float((unsigned)(acc[r] & 0xffffffffULL));
        const float hi = __uint_as_float((unsigned)(acc[r] >> 32));
        w_s[warp][r][lane] = lo + hi;
    }
    __syncthreads();

    for (int e = tid; e < ROWS_PER_CTA * T_BATCH; e += blockDim.x) {
        const int r = e >> 5;
        const int t = e & 31;
        float s = 0.f;
        #pragma unroll
        for (int w = 0; w < WARPS; w++) s += w_s[w][r][t];
        out[t * OUT_DIM + o0 + r] = s;
    }
}

extern "C" void kernel_launch(void* const* d_in, const int* in_sizes, int n_in,
                              void* d_out, int out_size) {
    const float* x      = (const float*)d_in[0];
    const int*   tern   = (const int*)d_in[1];
    const float* scales = (const float*)d_in[2];
    float*       out    = (float*)d_out;

    ternary_linear_kernel<<<OUT_DIM / ROWS_PER_CTA, 256>>>(x, tern, scales, out);
}

// round 2
// speedup vs baseline: 1.3819x; 1.3819x over previous
#include <cuda_runtime.h>
#include <cstdint>

#define OUT_DIM 8192
#define IN_DIM  8192
#define GS      128
#define NGRP    (IN_DIM / GS)      /* 64 scale groups per output row */
#define O_WARP  8                  /* output rows per warp tile */
#define T_WARP  8                  /* batch rows per warp tile */
#define CHUNK   128                /* K per chunk == GS (one scale per (o,chunk)) */
#define NCHUNK  (IN_DIM / CHUNK)   /* 64 */
#define O_CTA   16                 /* 8 warps = 2 o-groups x 4 t-groups */
#define GRID    (OUT_DIM / O_CTA)  /* 512 CTAs */

// Packed dual FMA / MUL on the sm_103a f32x2 pipe.
__device__ __forceinline__ void ffma2(unsigned long long &acc,
                                      unsigned long long a,
                                      unsigned long long b) {
    asm("fma.rn.f32x2 %0, %1, %2, %0;" : "+l"(acc) : "l"(a), "l"(b));
}
__device__ __forceinline__ unsigned long long pack2(float lo, float hi) {
    unsigned long long r;
    asm("mov.b64 %0, {%1, %2};" : "=l"(r) : "f"(lo), "f"(hi));
    return r;
}
__device__ __forceinline__ unsigned long long mul2(unsigned long long a,
                                                   unsigned long long b) {
    unsigned long long r;
    asm("mul.rn.f32x2 %0, %1, %2;" : "=l"(r) : "l"(a), "l"(b));
    return r;
}

__global__ __launch_bounds__(256, 1)
void ternary_linear_regs(const float* __restrict__ x,
                         const int*   __restrict__ tern,
                         const float* __restrict__ scales,
                         float*       __restrict__ out)
{
    const int tid  = threadIdx.x;
    const int lane = tid & 31;
    const int warp = tid >> 5;
    const int og   = warp >> 2;              // 0..1
    const int tg   = warp & 3;               // 0..3
    const int o_base = blockIdx.x * O_CTA + og * O_WARP;
    const int t_base = tg * T_WARP;
    const int kq   = lane * 4;               // lane owns K offsets kq..kq+3 within a chunk

    unsigned long long acc[O_WARP][T_WARP];  // f32x2 accumulators (even/odd K)
    #pragma unroll
    for (int o = 0; o < O_WARP; o++)
        #pragma unroll
        for (int t = 0; t < T_WARP; t++) acc[o][t] = 0ULL;

    // Software-pipelined ternary prefetch (depth 1): coalesced 512B/warp per row.
    int4 tv[O_WARP];
    #pragma unroll
    for (int o = 0; o < O_WARP; o++)
        tv[o] = *reinterpret_cast<const int4*>(tern + (o_base + o) * IN_DIM + kq);

    for (int ch = 0; ch < NCHUNK; ch++) {
        const int k0 = ch * CHUNK;

        // Dequantize current chunk into registers: w = float(tern) * scale.
        // Chunk == scale group, so one uniform scale per (o, chunk).
        unsigned long long wp[O_WARP][2];
        #pragma unroll
        for (int o = 0; o < O_WARP; o++) {
            const float s = __ldg(scales + (o_base + o) * NGRP + ch);
            const unsigned long long ss = pack2(s, s);
            const int4 v = tv[o];
            wp[o][0] = mul2(pack2((float)v.x, (float)v.y), ss);
            wp[o][1] = mul2(pack2((float)v.z, (float)v.w), ss);
        }

        // Prefetch next chunk's ternary (hides DRAM latency under the FFMA2 block).
        if (ch + 1 < NCHUNK) {
            #pragma unroll
            for (int o = 0; o < O_WARP; o++)
                tv[o] = *reinterpret_cast<const int4*>(
                    tern + (o_base + o) * IN_DIM + k0 + CHUNK + kq);
        }

        // 128 FFMA2 per chunk: x loaded once per t (L2-hot), reused across 8 o.
        #pragma unroll
        for (int t = 0; t < T_WARP; t++) {
            const float4 xq = *reinterpret_cast<const float4*>(
                x + (t_base + t) * IN_DIM + k0 + kq);
            const unsigned long long x01 = pack2(xq.x, xq.y);
            const unsigned long long x23 = pack2(xq.z, xq.w);
            #pragma unroll
            for (int o = 0; o < O_WARP; o++) {
                ffma2(acc[o][t], wp[o][0], x01);
                ffma2(acc[o][t], wp[o][1], x23);
            }
        }
    }

    // Fold f32x2 halves, then reduce the K dimension across lanes (butterfly).
    float r[O_WARP * T_WARP];
    #pragma unroll
    for (int o = 0; o < O_WARP; o++)
        #pragma unroll
        for (int t = 0; t < T_WARP; t++) {
            const float lo = __uint_as_float((unsigned)(acc[o][t] & 0xffffffffULL));
            const float hi = __uint_as_float((unsigned)(acc[o][t] >> 32));
            r[o * T_WARP + t] = lo + hi;
        }

    #pragma unroll
    for (int m = 16; m >= 1; m >>= 1)
        #pragma unroll
        for (int i = 0; i < O_WARP * T_WARP; i++)
            r[i] += __shfl_xor_sync(0xffffffffu, r[i], m);

    // 64 outputs per warp; lane idx>>1 writes each (2 STG per lane).
    #pragma unroll
    for (int o = 0; o < O_WARP; o++)
        #pragma unroll
        for (int t = 0; t < T_WARP; t++) {
            const int idx = o * T_WARP + t;
            if (lane == (idx >> 1))
                out[(t_base + t) * OUT_DIM + o_base + o] = r[idx];
        }
}

extern "C" void kernel_launch(void* const* d_in, const int* in_sizes, int n_in,
                              void* d_out, int out_size) {
    const float* x      = (const float*)d_in[0];
    const int*   tern   = (const int*)d_in[1];
    const float* scales = (const float*)d_in[2];
    float*       out    = (float*)d_out;

    ternary_linear_regs<<<GRID, 256>>>(x, tern, scales, out);
}

// round 3
// speedup vs baseline: 3.1613x; 2.2876x over previous
#include <cuda_runtime.h>
#include <cuda_fp16.h>
#include <cstdint>

#define OUT_DIM 8192
#define IN_DIM  8192
#define NGRP    64                 /* scale groups per output row (GS=128) */
#define KSTEPS  512                /* IN_DIM / 16 */
#define DEPTH_A 8                  /* A (ternary) prefetch depth: DRAM latency */
#define DEPTH_B 4                  /* B (xfrag) prefetch depth: L2 latency */

// x pre-packed in exact m16n8k16 B-fragment order: [kstep][ntile][lane] -> 2 regs.
__device__ uint2 g_xfrag[KSTEPS * 4 * 32];

__global__ void xconv_kernel(const float* __restrict__ x) {
    const int idx  = blockIdx.x * blockDim.x + threadIdx.x;   // 0..65535
    const int lane = idx & 31;
    const int nt   = (idx >> 5) & 3;
    const int kt   = idx >> 7;
    const int g    = lane >> 2;
    const int tig  = lane & 3;
    const int t    = nt * 8 + g;
    const int k0   = kt * 16 + tig * 2;
    __half2 h0 = __floats2half2_rn(x[t * IN_DIM + k0],     x[t * IN_DIM + k0 + 1]);
    __half2 h1 = __floats2half2_rn(x[t * IN_DIM + k0 + 8], x[t * IN_DIM + k0 + 9]);
    uint2 v;
    v.x = *reinterpret_cast<unsigned*>(&h0);
    v.y = *reinterpret_cast<unsigned*>(&h1);
    g_xfrag[idx] = v;
}

// t in {-1,0,1}: low 16 bits of (t<<14) are exactly fp16(2t). Pack a pair, then
// scale by half2(s/2): products are +-fp16(s), exact (multiply by +-2 shifts exp).
__device__ __forceinline__ unsigned cvt_pair(int2 v, unsigned sh2) {
    unsigned u0 = (unsigned)v.x << 14;
    unsigned u1 = (unsigned)v.y << 14;
    unsigned p;
    asm("prmt.b32 %0, %1, %2, 0x5410;" : "=r"(p) : "r"(u0), "r"(u1));
    asm("mul.rn.f16x2 %0, %1, %2;" : "=r"(p) : "r"(p), "r"(sh2));
    return p;
}

__device__ __forceinline__ void mma16816(float c[4], unsigned a0, unsigned a1,
                                         unsigned a2, unsigned a3,
                                         unsigned b0, unsigned b1) {
    asm("mma.sync.aligned.m16n8k16.row.col.f32.f16.f16.f32 "
        "{%0,%1,%2,%3}, {%4,%5,%6,%7}, {%8,%9}, {%0,%1,%2,%3};"
        : "+f"(c[0]), "+f"(c[1]), "+f"(c[2]), "+f"(c[3])
        : "r"(a0), "r"(a1), "r"(a2), "r"(a3), "r"(b0), "r"(b1));
}

__global__ __launch_bounds__(128, 1)
void tmma_kernel(const int* __restrict__ tern,
                 const float* __restrict__ scales,
                 float* __restrict__ out)
{
    const int lane = threadIdx.x & 31;
    const int warp = threadIdx.x >> 5;
    const int g    = lane >> 2;
    const int tig  = lane & 3;
    const int o_tile = blockIdx.x * 64 + warp * 16;   // warp owns 16 o-rows, all 32 t
    const int row0 = o_tile + g;
    const int row1 = row0 + 8;

    const int* pA0 = tern + (long)row0 * IN_DIM + tig * 2;   // a0/a2 stream
    const int* pA1 = tern + (long)row1 * IN_DIM + tig * 2;   // a1/a3 stream

    float acc[4][4];
    #pragma unroll
    for (int n = 0; n < 4; n++)
        #pragma unroll
        for (int i = 0; i < 4; i++) acc[n][i] = 0.f;

    int2  abuf[DEPTH_A][4];
    uint2 bbuf[DEPTH_B][4];

    #pragma unroll
    for (int d = 0; d < DEPTH_A; d++) {
        abuf[d][0] = __ldg((const int2*)(pA0 + d * 16));
        abuf[d][1] = __ldg((const int2*)(pA1 + d * 16));
        abuf[d][2] = __ldg((const int2*)(pA0 + d * 16 + 8));
        abuf[d][3] = __ldg((const int2*)(pA1 + d * 16 + 8));
    }
    #pragma unroll
    for (int d = 0; d < DEPTH_B; d++)
        #pragma unroll
        for (int nt = 0; nt < 4; nt++)
            bbuf[d][nt] = g_xfrag[(d * 4 + nt) * 32 + lane];

    unsigned sh0 = 0, sh1 = 0;

    #pragma unroll 8
    for (int ks = 0; ks < KSTEPS; ks++) {
        if ((ks & 7) == 0) {                       // new scale group (GS=128 = 8 ksteps)
            const int grp = ks >> 3;
            const float s0 = __ldg(scales + row0 * NGRP + grp) * 0.5f;
            const float s1 = __ldg(scales + row1 * NGRP + grp) * 0.5f;
            const __half2 p0 = __half2half2(__float2half_rn(s0));
            const __half2 p1 = __half2half2(__float2half_rn(s1));
            sh0 = *reinterpret_cast<const unsigned*>(&p0);
            sh1 = *reinterpret_cast<const unsigned*>(&p1);
        }

        const int ia = ks & (DEPTH_A - 1);
        const int ib = ks & (DEPTH_B - 1);

        const int2 ra0 = abuf[ia][0], ra1 = abuf[ia][1];
        const int2 ra2 = abuf[ia][2], ra3 = abuf[ia][3];
        uint2 rb[4];
        #pragma unroll
        for (int nt = 0; nt < 4; nt++) rb[nt] = bbuf[ib][nt];

        // Refill pipelines (predicated off at the tail).
        const int ka = ks + DEPTH_A;
        if (ka < KSTEPS) {
            abuf[ia][0] = __ldg((const int2*)(pA0 + ka * 16));
            abuf[ia][1] = __ldg((const int2*)(pA1 + ka * 16));
            abuf[ia][2] = __ldg((const int2*)(pA0 + ka * 16 + 8));
            abuf[ia][3] = __ldg((const int2*)(pA1 + ka * 16 + 8));
        }
        const int kb = ks + DEPTH_B;
        if (kb < KSTEPS) {
            #pragma unroll
            for (int nt = 0; nt < 4; nt++)
                bbuf[ib][nt] = g_xfrag[(kb * 4 + nt) * 32 + lane];
        }

        // Dequant to fp16 (scaled) and issue 4 HMMAs (n = 32 t).
        const unsigned a0 = cvt_pair(ra0, sh0);
        const unsigned a1 = cvt_pair(ra1, sh1);
        const unsigned a2 = cvt_pair(ra2, sh0);
        const unsigned a3 = cvt_pair(ra3, sh1);
        #pragma unroll
        for (int nt = 0; nt < 4; nt++)
            mma16816(acc[nt], a0, a1, a2, a3, rb[nt].x, rb[nt].y);
    }

    // C frag: c0,c1 -> (row0, t, t+1); c2,c3 -> (row1, t, t+1), t = nt*8 + tig*2.
    #pragma unroll
    for (int nt = 0; nt < 4; nt++) {
        const int t = nt * 8 + tig * 2;
        out[(long)t       * OUT_DIM + row0] = acc[nt][0];
        out[(long)(t + 1) * OUT_DIM + row0] = acc[nt][1];
        out[(long)t       * OUT_DIM + row1] = acc[nt][2];
        out[(long)(t + 1) * OUT_DIM + row1] = acc[nt][3];
    }
}

extern "C" void kernel_launch(void* const* d_in, const int* in_sizes, int n_in,
                              void* d_out, int out_size) {
    const float* x      = (const float*)d_in[0];
    const int*   tern   = (const int*)d_in[1];
    const float* scales = (const float*)d_in[2];
    float*       out    = (float*)d_out;

    xconv_kernel<<<256, 256>>>(x);
    tmma_kernel<<<OUT_DIM / 64, 128>>>(tern, scales, out);
}

// round 4
// speedup vs baseline: 4.0599x; 1.2843x over previous
#include <cuda_runtime.h>
#include <cuda_fp16.h>
#include <cstdint>

#define OUT_DIM 8192
#define IN_DIM  8192
#define NGRP    64                 /* scale groups per output row (GS=128) */
#define KSTEPS  512                /* IN_DIM / 16 */
#define KSPLIT  4                  /* K split across the 4 warps of a CTA */
#define KS_W    (KSTEPS / KSPLIT)  /* 128 ksteps per warp */
#define DEPTH_A 8
#define DEPTH_B 4

// x pre-packed in exact m16n8k16 B-fragment order: [kstep][ntile][lane] -> 2 regs.
__device__ uint2 g_xfrag[KSTEPS * 4 * 32];

__global__ void xconv_kernel(const float* __restrict__ x) {
    const int idx  = blockIdx.x * blockDim.x + threadIdx.x;   // 0..65535
    const int lane = idx & 31;
    const int nt   = (idx >> 5) & 3;
    const int kt   = idx >> 7;
    const int g    = lane >> 2;
    const int tig  = lane & 3;
    const int t    = nt * 8 + g;
    const int k0   = kt * 16 + tig * 2;
    __half2 h0 = __floats2half2_rn(x[t * IN_DIM + k0],     x[t * IN_DIM + k0 + 1]);
    __half2 h1 = __floats2half2_rn(x[t * IN_DIM + k0 + 8], x[t * IN_DIM + k0 + 9]);
    uint2 v;
    v.x = *reinterpret_cast<unsigned*>(&h0);
    v.y = *reinterpret_cast<unsigned*>(&h1);
    g_xfrag[idx] = v;
}

// t in {-1,0,1}: low 16 bits of (t<<14) are exactly fp16(2t). Pack a pair, then
// scale by half2(s/2): products are +-fp16(s), exact (x2 only shifts the exponent).
__device__ __forceinline__ unsigned cvt_pair(int2 v, unsigned sh2) {
    unsigned u0 = (unsigned)v.x << 14;
    unsigned u1 = (unsigned)v.y << 14;
    unsigned p;
    asm("prmt.b32 %0, %1, %2, 0x5410;" : "=r"(p) : "r"(u0), "r"(u1));
    asm("mul.rn.f16x2 %0, %1, %2;" : "=r"(p) : "r"(p), "r"(sh2));
    return p;
}

__device__ __forceinline__ void mma16816(float c[4], unsigned a0, unsigned a1,
                                         unsigned a2, unsigned a3,
                                         unsigned b0, unsigned b1) {
    asm("mma.sync.aligned.m16n8k16.row.col.f32.f16.f16.f32 "
        "{%0,%1,%2,%3}, {%4,%5,%6,%7}, {%8,%9}, {%0,%1,%2,%3};"
        : "+f"(c[0]), "+f"(c[1]), "+f"(c[2]), "+f"(c[3])
        : "r"(a0), "r"(a1), "r"(a2), "r"(a3), "r"(b0), "r"(b1));
}

__global__ __launch_bounds__(128)
void tmma_kernel(const int* __restrict__ tern,
                 const float* __restrict__ scales,
                 float* __restrict__ out)
{
    const int lane = threadIdx.x & 31;
    const int kg   = threadIdx.x >> 5;       // warp = K quarter (0..3)
    const int g    = lane >> 2;
    const int tig  = lane & 3;
    const int o_tile = blockIdx.x * 16;      // CTA owns 16 o-rows x all 32 t x full K
    const int row0 = o_tile + g;
    const int row1 = row0 + 8;
    const int kbase = kg * KS_W;             // this warp's first global kstep

    const int* pA0 = tern + (long)row0 * IN_DIM + kbase * 16 + tig * 2;
    const int* pA1 = tern + (long)row1 * IN_DIM + kbase * 16 + tig * 2;

    float acc[4][4];
    #pragma unroll
    for (int n = 0; n < 4; n++)
        #pragma unroll
        for (int i = 0; i < 4; i++) acc[n][i] = 0.f;

    int2  abuf[DEPTH_A][4];
    uint2 bbuf[DEPTH_B][4];

    #pragma unroll
    for (int d = 0; d < DEPTH_A; d++) {
        abuf[d][0] = __ldg((const int2*)(pA0 + d * 16));
        abuf[d][1] = __ldg((const int2*)(pA1 + d * 16));
        abuf[d][2] = __ldg((const int2*)(pA0 + d * 16 + 8));
        abuf[d][3] = __ldg((const int2*)(pA1 + d * 16 + 8));
    }
    #pragma unroll
    for (int d = 0; d < DEPTH_B; d++)
        #pragma unroll
        for (int nt = 0; nt < 4; nt++)
            bbuf[d][nt] = g_xfrag[((kbase + d) * 4 + nt) * 32 + lane];

    unsigned sh0 = 0, sh1 = 0;

    #pragma unroll 8
    for (int ks = 0; ks < KS_W; ks++) {
        if ((ks & 7) == 0) {                 // new scale group (GS=128 = 8 ksteps)
            const int grp = (kbase + ks) >> 3;
            const float s0 = __ldg(scales + row0 * NGRP + grp) * 0.5f;
            const float s1 = __ldg(scales + row1 * NGRP + grp) * 0.5f;
            const __half2 p0 = __half2half2(__float2half_rn(s0));
            const __half2 p1 = __half2half2(__float2half_rn(s1));
            sh0 = *reinterpret_cast<const unsigned*>(&p0);
            sh1 = *reinterpret_cast<const unsigned*>(&p1);
        }

        const int ia = ks & (DEPTH_A - 1);
        const int ib = ks & (DEPTH_B - 1);

        const int2 ra0 = abuf[ia][0], ra1 = abuf[ia][1];
        const int2 ra2 = abuf[ia][2], ra3 = abuf[ia][3];
        uint2 rb[4];
        #pragma unroll
        for (int nt = 0; nt < 4; nt++) rb[nt] = bbuf[ib][nt];

        const int ka = ks + DEPTH_A;
        if (ka < KS_W) {
            abuf[ia][0] = __ldg((const int2*)(pA0 + ka * 16));
            abuf[ia][1] = __ldg((const int2*)(pA1 + ka * 16));
            abuf[ia][2] = __ldg((const int2*)(pA0 + ka * 16 + 8));
            abuf[ia][3] = __ldg((const int2*)(pA1 + ka * 16 + 8));
        }
        const int kb = ks + DEPTH_B;
        if (kb < KS_W) {
            #pragma unroll
            for (int nt = 0; nt < 4; nt++)
                bbuf[ib][nt] = g_xfrag[((kbase + kb) * 4 + nt) * 32 + lane];
        }

        const unsigned a0 = cvt_pair(ra0, sh0);
        const unsigned a1 = cvt_pair(ra1, sh1);
        const unsigned a2 = cvt_pair(ra2, sh0);
        const unsigned a3 = cvt_pair(ra3, sh1);
        #pragma unroll
        for (int nt = 0; nt < 4; nt++)
            mma16816(acc[nt], a0, a1, a2, a3, rb[nt].x, rb[nt].y);
    }

    // Deterministic cross-warp K reduction through smem (fixed summation order).
    __shared__ float red[KSPLIT][32][16];
    #pragma unroll
    for (int nt = 0; nt < 4; nt++)
        #pragma unroll
        for (int i = 0; i < 4; i++)
            red[kg][lane][nt * 4 + i] = acc[nt][i];
    __syncthreads();

    if (kg == 0) {
        #pragma unroll
        for (int nt = 0; nt < 4; nt++) {
            const int t = nt * 8 + tig * 2;
            #pragma unroll
            for (int i = 0; i < 4; i++) {
                const int idx = nt * 4 + i;
                float s = red[0][lane][idx];
                #pragma unroll
                for (int w = 1; w < KSPLIT; w++) s += red[w][lane][idx];
                const int row = (i < 2) ? row0 : row1;
                const int tt  = t + (i & 1);
                out[(long)tt * OUT_DIM + row] = s;
            }
        }
    }
}

extern "C" void kernel_launch(void* const* d_in, const int* in_sizes, int n_in,
                              void* d_out, int out_size) {
    const float* x      = (const float*)d_in[0];
    const int*   tern   = (const int*)d_in[1];
    const float* scales = (const float*)d_in[2];
    float*       out    = (float*)d_out;

    xconv_kernel<<<256, 256>>>(x);
    tmma_kernel<<<OUT_DIM / 16, 128>>>(tern, scales, out);
}

// round 5
// speedup vs baseline: 5.0441x; 1.2424x over previous
#include <cuda_runtime.h>
#include <cuda_fp16.h>
#include <cstdint>

#define OUT_DIM 8192
#define IN_DIM  8192
#define NGRP    64                 /* scale groups per output row (GS=128) */
#define KSTEPS  512                /* IN_DIM / 16 */
#define KSPLIT  4                  /* K split across the 4 warps of a CTA */
#define KS_W    (KSTEPS / KSPLIT)  /* 128 ksteps per warp */
#define DEPTH_A 4
#define DEPTH_B 4

// x pre-packed per (kstep, lane): 2 uint4 = fragments for all 4 ntiles.
// k is PERMUTED inside each 16-wide kstep: fragment positions
// (2tig, 2tig+1, 2tig+8, 2tig+9) hold physical k (4tig, 4tig+1, 4tig+2, 4tig+3).
// A uses the same permutation, so the MMA result is unchanged.
__device__ uint4 g_xfrag[KSTEPS * 32 * 2];

__global__ void xconv_kernel(const float* __restrict__ x) {
    const int idx  = blockIdx.x * blockDim.x + threadIdx.x;   // 0..16383
    const int lane = idx & 31;
    const int kt   = idx >> 5;
    const int g    = lane >> 2;
    const int tig  = lane & 3;
    const int k0   = kt * 16 + tig * 4;

    unsigned w[8];
    #pragma unroll
    for (int nt = 0; nt < 4; nt++) {
        const int n = nt * 8 + g;                 // batch row
        const float4 a = *reinterpret_cast<const float4*>(x + n * IN_DIM + k0);
        __half2 lo = __floats2half2_rn(a.x, a.y); // b0: positions 2tig,2tig+1
        __half2 hi = __floats2half2_rn(a.z, a.w); // b1: positions 2tig+8,2tig+9
        w[nt * 2]     = *reinterpret_cast<unsigned*>(&lo);
        w[nt * 2 + 1] = *reinterpret_cast<unsigned*>(&hi);
    }
    g_xfrag[idx * 2]     = make_uint4(w[0], w[1], w[2], w[3]);
    g_xfrag[idx * 2 + 1] = make_uint4(w[4], w[5], w[6], w[7]);
}

// t in {-1,0,1}: low 16 bits of (t<<14) are exactly fp16(2t). Pack a pair, then
// scale by half2(s/2): products are +-fp16(s), exact (x2 only shifts the exponent).
__device__ __forceinline__ unsigned cvt_pair(unsigned t0, unsigned t1, unsigned sh2) {
    unsigned u0 = t0 << 14;
    unsigned u1 = t1 << 14;
    unsigned p;
    asm("prmt.b32 %0, %1, %2, 0x5410;" : "=r"(p) : "r"(u0), "r"(u1));
    asm("mul.rn.f16x2 %0, %1, %2;" : "=r"(p) : "r"(p), "r"(sh2));
    return p;
}

__device__ __forceinline__ void mma16816(float c[4], unsigned a0, unsigned a1,
                                         unsigned a2, unsigned a3,
                                         unsigned b0, unsigned b1) {
    asm("mma.sync.aligned.m16n8k16.row.col.f32.f16.f16.f32 "
        "{%0,%1,%2,%3}, {%4,%5,%6,%7}, {%8,%9}, {%0,%1,%2,%3};"
        : "+f"(c[0]), "+f"(c[1]), "+f"(c[2]), "+f"(c[3])
        : "r"(a0), "r"(a1), "r"(a2), "r"(a3), "r"(b0), "r"(b1));
}

__global__ __launch_bounds__(128, 4)
void tmma_kernel(const int* __restrict__ tern,
                 const float* __restrict__ scales,
                 float* __restrict__ out)
{
    const int lane = threadIdx.x & 31;
    const int kg   = threadIdx.x >> 5;       // warp = K quarter (0..3)
    const int g    = lane >> 2;
    const int tig  = lane & 3;
    const int o_tile = blockIdx.x * 16;      // CTA: 16 o-rows x all 32 t x full K
    const int row0 = o_tile + g;
    const int row1 = row0 + 8;
    const int kbase = kg * KS_W;

    // int4 per kstep per row-stream: holds (a0 pair | a2 pair) under permutation.
    const int4* pA0 = reinterpret_cast<const int4*>(tern + (long)row0 * IN_DIM + kbase * 16 + tig * 4);
    const int4* pA1 = reinterpret_cast<const int4*>(tern + (long)row1 * IN_DIM + kbase * 16 + tig * 4);
    const uint4* pB = g_xfrag + (long)(kbase * 32 + lane) * 2;

    float acc[4][4];
    #pragma unroll
    for (int n = 0; n < 4; n++)
        #pragma unroll
        for (int i = 0; i < 4; i++) acc[n][i] = 0.f;

    int4  abuf[DEPTH_A][2];
    uint4 bbuf[DEPTH_B][2];

    #pragma unroll
    for (int d = 0; d < DEPTH_A; d++) {
        abuf[d][0] = __ldg(pA0 + d * 4);     // int4 stride 4 per kstep (16 ints)
        abuf[d][1] = __ldg(pA1 + d * 4);
    }
    #pragma unroll
    for (int d = 0; d < DEPTH_B; d++) {
        bbuf[d][0] = pB[d * 64];             // uint4 stride 64 per kstep (32 lanes x 2)
        bbuf[d][1] = pB[d * 64 + 1];
    }

    unsigned sh0 = 0, sh1 = 0;

    #pragma unroll 8
    for (int ks = 0; ks < KS_W; ks++) {
        if ((ks & 7) == 0) {                 // new scale group (GS=128 = 8 ksteps)
            const int grp = (kbase + ks) >> 3;
            const float s0 = __ldg(scales + row0 * NGRP + grp) * 0.5f;
            const float s1 = __ldg(scales + row1 * NGRP + grp) * 0.5f;
            const __half2 p0 = __half2half2(__float2half_rn(s0));
            const __half2 p1 = __half2half2(__float2half_rn(s1));
            sh0 = *reinterpret_cast<const unsigned*>(&p0);
            sh1 = *reinterpret_cast<const unsigned*>(&p1);
        }

        const int ia = ks & (DEPTH_A - 1);
        const int ib = ks & (DEPTH_B - 1);

        const int4  va0 = abuf[ia][0];
        const int4  va1 = abuf[ia][1];
        const uint4 vb0 = bbuf[ib][0];
        const uint4 vb1 = bbuf[ib][1];

        const int ka = ks + DEPTH_A;
        if (ka < KS_W) {
            abuf[ia][0] = __ldg(pA0 + ka * 4);
            abuf[ia][1] = __ldg(pA1 + ka * 4);
        }
        const int kb = ks + DEPTH_B;
        if (kb < KS_W) {
            bbuf[ib][0] = pB[kb * 64];
            bbuf[ib][1] = pB[kb * 64 + 1];
        }

        const unsigned a0 = cvt_pair((unsigned)va0.x, (unsigned)va0.y, sh0);
        const unsigned a2 = cvt_pair((unsigned)va0.z, (unsigned)va0.w, sh0);
        const unsigned a1 = cvt_pair((unsigned)va1.x, (unsigned)va1.y, sh1);
        const unsigned a3 = cvt_pair((unsigned)va1.z, (unsigned)va1.w, sh1);

        mma16816(acc[0], a0, a1, a2, a3, vb0.x, vb0.y);
        mma16816(acc[1], a0, a1, a2, a3, vb0.z, vb0.w);
        mma16816(acc[2], a0, a1, a2, a3, vb1.x, vb1.y);
        mma16816(acc[3], a0, a1, a2, a3, vb1.z, vb1.w);
    }

    // Deterministic cross-warp K reduction through smem (fixed summation order).
    __shared__ float red[KSPLIT][32][16];
    #pragma unroll
    for (int nt = 0; nt < 4; nt++)
        #pragma unroll
        for (int i = 0; i < 4; i++)
            red[kg][lane][nt * 4 + i] = acc[nt][i];
    __syncthreads();

    if (kg == 0) {
        #pragma unroll
        for (int nt = 0; nt < 4; nt++) {
            const int t = nt * 8 + tig * 2;
            #pragma unroll
            for (int i = 0; i < 4; i++) {
                const int idx = nt * 4 + i;
                float s = red[0][lane][idx];
                #pragma unroll
                for (int w = 1; w < KSPLIT; w++) s += red[w][lane][idx];
                const int row = (i < 2) ? row0 : row1;
                const int tt  = t + (i & 1);
                out[(long)tt * OUT_DIM + row] = s;
            }
        }
    }
}

extern "C" void kernel_launch(void* const* d_in, const int* in_sizes, int n_in,
                              void* d_out, int out_size) {
    const float* x      = (const float*)d_in[0];
    const int*   tern   = (const int*)d_in[1];
    const float* scales = (const float*)d_in[2];
    float*       out    = (float*)d_out;

    xconv_kernel<<<64, 256>>>(x);
    tmma_kernel<<<OUT_DIM / 16, 128>>>(tern, scales, out);
}